// round 14
// baseline (speedup 1.0000x reference)
#include <cuda_runtime.h>
#include <cstdint>

// Problem constants
#define N_TOK  262144
#define K_CB   1024
#define D_EMB  64
#define DECAY  0.99f
#define EPSV   1e-5f
#define COMMIT 0.25f

// Output layout (float32 blob, reference return order)
#define OFF_Q    0
#define OFF_LOSS 16777216
#define OFF_IDX  16777217
#define OFF_CB   17039361   // odd -> only 4-byte aligned
#define OFF_CS   17104897
#define OFF_EW   17105921   // odd -> only 4-byte aligned

#define SEGW 20   // padded fragment segment: 16 payload words + 4 pad = 80B

// Scratch (device globals; no allocations allowed)
__device__ float    g_dw[K_CB * D_EMB];
__device__ float    g_counts[K_CB];
__device__ float    g_loss;
__device__ float    g_cnorm[K_CB];
__device__ float    g_n;
// codebook tf32, PADDED fragment-major. global seg = (k>>3)*32 + (k&7)*4 + (d&3);
// word m=d>>2 of seg holds k-dim d. 4096 segs * 20 words = 320KB.
__device__ __align__(16) unsigned g_cbtp[(K_CB / 8) * 32 * SEGW];
__device__ unsigned g_xmax2;               // max ||x||^2 (float bits)
__device__ unsigned g_cmax2;               // max ||c||^2 (float bits)

// ---------------------------------------------------------------------------
__device__ __forceinline__ unsigned f2tf32(float f) {
    unsigned r; asm("cvt.rna.tf32.f32 %0, %1;" : "=r"(r) : "f"(f)); return r;
}

__device__ __forceinline__ void mma_tf32(float c[4], const unsigned a[4],
                                         unsigned b0, unsigned b1) {
    asm volatile(
        "mma.sync.aligned.m16n8k8.row.col.f32.tf32.tf32.f32 "
        "{%0,%1,%2,%3}, {%4,%5,%6,%7}, {%8,%9}, {%0,%1,%2,%3};"
        : "+f"(c[0]), "+f"(c[1]), "+f"(c[2]), "+f"(c[3])
        : "r"(a[0]), "r"(a[1]), "r"(a[2]), "r"(a[3]), "r"(b0), "r"(b1));
}

// Exact distance, bit-identical to the validated R2 chain ordering.
__device__ __forceinline__ float exact_d(const float4* x4, const float* crow, float cn) {
    const float4* c4 = reinterpret_cast<const float4*>(crow);
    float s0 = 0.f, s1 = 0.f, s2 = 0.f, s3 = 0.f;
#pragma unroll
    for (int i = 0; i < 16; i++) {
        float4 c = c4[i];
        s0 = fmaf(x4[i].x, c.x, s0);
        s1 = fmaf(x4[i].y, c.y, s1);
        s2 = fmaf(x4[i].z, c.z, s2);
        s3 = fmaf(x4[i].w, c.w, s3);
    }
    return cn - 2.0f * ((s0 + s1) + (s2 + s3));
}

// ---------------------------------------------------------------------------
__global__ void vq_zero_kernel() {
    int i = blockIdx.x * blockDim.x + threadIdx.x;
    if (i < K_CB * D_EMB) g_dw[i] = 0.0f;
    if (i < K_CB)         g_counts[i] = 0.0f;
    if (i == 0) { g_loss = 0.0f; g_xmax2 = 0u; g_cmax2 = 0u; }
}

// ---------------------------------------------------------------------------
// Prep codebook: exact cnorm (R2 chain), tf32 PADDED fragment-major scatter,
// max ||c||^2. One block of 1024 threads (one code per thread).
// ---------------------------------------------------------------------------
__global__ void __launch_bounds__(K_CB)
vq_prep_cb_kernel(const float* __restrict__ codebook) {
    __shared__ float s_m[32];
    int k = threadIdx.x;
    const float4* c = reinterpret_cast<const float4*>(codebook + (size_t)k * D_EMB);
    float s0 = 0.f, s1 = 0.f, s2 = 0.f, s3 = 0.f;
#pragma unroll
    for (int i = 0; i < 16; i++) {
        float4 v = c[i];
        s0 += v.x * v.x; s1 += v.y * v.y;
        s2 += v.z * v.z; s3 += v.w * v.w;
    }
    float cn = (s0 + s1) + (s2 + s3);
    g_cnorm[k] = cn;
    const int segbase = ((k >> 3) << 5) + ((k & 7) << 2);
#pragma unroll
    for (int d = 0; d < D_EMB; d++)
        g_cbtp[(size_t)(segbase + (d & 3)) * SEGW + (d >> 2)] =
            f2tf32(codebook[(size_t)k * D_EMB + d]);
    float m = cn;
#pragma unroll
    for (int o = 16; o > 0; o >>= 1) m = fmaxf(m, __shfl_xor_sync(~0u, m, o));
    if ((k & 31) == 0) s_m[k >> 5] = m;
    __syncthreads();
    if (k == 0) {
        float t = s_m[0];
        for (int w = 1; w < 32; w++) t = fmaxf(t, s_m[w]);
        atomicMax(&g_cmax2, __float_as_uint(t));
    }
}

// ---------------------------------------------------------------------------
// Prep inputs: max ||x||^2 over all tokens.
// ---------------------------------------------------------------------------
__global__ void __launch_bounds__(256)
vq_prep_x_kernel(const float* __restrict__ inputs) {
    __shared__ float s_m[8];
    int t = blockIdx.x * 256 + threadIdx.x;
    const float4* x = reinterpret_cast<const float4*>(inputs + (size_t)t * D_EMB);
    float s = 0.f;
#pragma unroll
    for (int i = 0; i < 16; i++) {
        float4 v = x[i];
        s += v.x * v.x + v.y * v.y + v.z * v.z + v.w * v.w;
    }
#pragma unroll
    for (int o = 16; o > 0; o >>= 1) s = fmaxf(s, __shfl_xor_sync(~0u, s, o));
    if ((threadIdx.x & 31) == 0) s_m[threadIdx.x >> 5] = s;
    __syncthreads();
    if (threadIdx.x == 0) {
        float m = s_m[0];
        for (int w = 1; w < 8; w++) m = fmaxf(m, s_m[w]);
        atomicMax(&g_xmax2, __float_as_uint(m));
    }
}

// ---------------------------------------------------------------------------
// Screen kernel — SINGLE progressive sweep + chunk-0 recollect:
//   chunks 0..7: GEMM (d~ bit-identical to R8/R11/R13), update per-row m1;
//     for ch>=1 collect j if d~ <= thr (thr = row-merged m1 after previous
//     chunk + 2W; monotone >= final threshold -> collected set is a SUPERSET
//     of the proven R8 window)
//   then re-stage chunk 0 only and collect with the final threshold.
// Exact rescore of candidates (validated R2 chain + first-min tie rule);
// overflow (> MAXCAND) falls back to per-thread exact full scan.
// Fused epilogue: quantized gather, idx, loss, dw atomics, counts (REDG).
// ---------------------------------------------------------------------------
#define SC_TPB   128
#define SC_TOKS  128
#define SC_CHUNK 128
#define MAXCAND  12
#define CHUNK_W  ((SC_CHUNK / 8) * 32 * SEGW)       // 10240 words per chunk
#define CHUNK_V  (CHUNK_W / 4)                       // 2560 uint4 per chunk

__global__ void __launch_bounds__(SC_TPB)
vq_screen_kernel(const float* __restrict__ inputs,
                 const float* __restrict__ codebook,
                 float* __restrict__ out) {
    __shared__ unsigned s_cb[CHUNK_W];               // 40KB staged chunk
    __shared__ float    s_cn[SC_CHUNK];
    __shared__ int      s_cnt[SC_TOKS];
    __shared__ int      s_list[SC_TOKS * MAXCAND];
    __shared__ float    s_red[SC_TPB / 32];

    const int tid  = threadIdx.x;
    const int warp = tid >> 5;
    const int lane = tid & 31;
    const int g    = lane >> 2;    // group id (row for A/C, code row for B)
    const int tq   = lane & 3;     // thread-in-group
    const int blkTok = blockIdx.x * SC_TOKS;
    const int tokBase = blkTok + warp * 32;

    if (tid < SC_TOKS) s_cnt[tid] = 0;

    // rigorous screen error bound (validated in R8)
    const float W = 2.4e-3f * sqrtf(__uint_as_float(g_xmax2))
                            * sqrtf(__uint_as_float(g_cmax2)) + 1e-3f;
    const float WIN = 2.0f * W;

    // A fragments for both token tiles, all 8 k-steps (held in regs)
    unsigned afr[2][8][4];
#pragma unroll
    for (int T = 0; T < 2; T++) {
        const int r0 = tokBase + T * 16 + g;
        const int r1 = r0 + 8;
        const float* x0 = inputs + (size_t)r0 * D_EMB;
        const float* x1 = inputs + (size_t)r1 * D_EMB;
#pragma unroll
        for (int q = 0; q < 8; q++) {
            afr[T][q][0] = f2tf32(x0[q * 8 + tq]);
            afr[T][q][1] = f2tf32(x1[q * 8 + tq]);
            afr[T][q][2] = f2tf32(x0[q * 8 + tq + 4]);
            afr[T][q][3] = f2tf32(x1[q * 8 + tq + 4]);
        }
    }

    float m1[2][2]  = {{3.4e38f, 3.4e38f}, {3.4e38f, 3.4e38f}};
    float thr[2][2] = {{3.4e38f, 3.4e38f}, {3.4e38f, 3.4e38f}};

    // pass 0: chunks 0..7 (collect for ch>=1); pass 1: chunk 0 recollect
    for (int pass = 0; pass < 2; pass++) {
        const int ch_lo = 0;
        const int ch_hi = (pass == 0) ? (K_CB / SC_CHUNK) : 1;
        for (int ch = ch_lo; ch < ch_hi; ch++) {
            const bool collect = (pass == 1) || (ch > 0);
            __syncthreads();
            {
                const uint4* src = reinterpret_cast<const uint4*>(g_cbtp + (size_t)ch * CHUNK_W);
                uint4* dst = reinterpret_cast<uint4*>(s_cb);
#pragma unroll
                for (int i = 0; i < CHUNK_V / SC_TPB; i++)
                    dst[tid + i * SC_TPB] = src[tid + i * SC_TPB];
            }
            if (tid < SC_CHUNK) s_cn[tid] = g_cnorm[ch * SC_CHUNK + tid];
            __syncthreads();

#pragma unroll 4
            for (int tile = 0; tile < SC_CHUNK / 8; tile++) {
                float c0[4] = {0.f, 0.f, 0.f, 0.f};
                float c1[4] = {0.f, 0.f, 0.f, 0.f};
                const unsigned* seg = s_cb + (((tile << 3) + g) * 4 + tq) * SEGW;
                uint4 w0 = *reinterpret_cast<const uint4*>(seg);
                uint4 w1 = *reinterpret_cast<const uint4*>(seg + 4);
                uint4 w2 = *reinterpret_cast<const uint4*>(seg + 8);
                uint4 w3 = *reinterpret_cast<const uint4*>(seg + 12);
                // q-order and operands identical to R8/R11/R13
                mma_tf32(c0, afr[0][0], w0.x, w0.y);  mma_tf32(c1, afr[1][0], w0.x, w0.y);
                mma_tf32(c0, afr[0][1], w0.z, w0.w);  mma_tf32(c1, afr[1][1], w0.z, w0.w);
                mma_tf32(c0, afr[0][2], w1.x, w1.y);  mma_tf32(c1, afr[1][2], w1.x, w1.y);
                mma_tf32(c0, afr[0][3], w1.z, w1.w);  mma_tf32(c1, afr[1][3], w1.z, w1.w);
                mma_tf32(c0, afr[0][4], w2.x, w2.y);  mma_tf32(c1, afr[1][4], w2.x, w2.y);
                mma_tf32(c0, afr[0][5], w2.z, w2.w);  mma_tf32(c1, afr[1][5], w2.z, w2.w);
                mma_tf32(c0, afr[0][6], w3.x, w3.y);  mma_tf32(c1, afr[1][6], w3.x, w3.y);
                mma_tf32(c0, afr[0][7], w3.z, w3.w);  mma_tf32(c1, afr[1][7], w3.z, w3.w);

                const int col0 = (tile << 3) + tq * 2;
                const int j0 = ch * SC_CHUNK + col0, j1 = j0 + 1;
                const float cn0 = s_cn[col0], cn1 = s_cn[col0 + 1];
                float dA0 = fmaf(-2.0f, c0[0], cn0), dA1 = fmaf(-2.0f, c0[1], cn1);
                float dA2 = fmaf(-2.0f, c0[2], cn0), dA3 = fmaf(-2.0f, c0[3], cn1);
                float dB0 = fmaf(-2.0f, c1[0], cn0), dB1 = fmaf(-2.0f, c1[1], cn1);
                float dB2 = fmaf(-2.0f, c1[2], cn0), dB3 = fmaf(-2.0f, c1[3], cn1);

                if (collect) {
                    const int s00 = warp * 32 + g;         // tile0 row g
                    const int s01 = s00 + 8;               // tile0 row g+8
                    const int s10 = s00 + 16;              // tile1 row g
                    const int s11 = s00 + 24;              // tile1 row g+8
                    if (dA0 <= thr[0][0]) { int p = atomicAdd(&s_cnt[s00], 1); if (p < MAXCAND) s_list[s00 * MAXCAND + p] = j0; }
                    if (dA1 <= thr[0][0]) { int p = atomicAdd(&s_cnt[s00], 1); if (p < MAXCAND) s_list[s00 * MAXCAND + p] = j1; }
                    if (dA2 <= thr[0][1]) { int p = atomicAdd(&s_cnt[s01], 1); if (p < MAXCAND) s_list[s01 * MAXCAND + p] = j0; }
                    if (dA3 <= thr[0][1]) { int p = atomicAdd(&s_cnt[s01], 1); if (p < MAXCAND) s_list[s01 * MAXCAND + p] = j1; }
                    if (dB0 <= thr[1][0]) { int p = atomicAdd(&s_cnt[s10], 1); if (p < MAXCAND) s_list[s10 * MAXCAND + p] = j0; }
                    if (dB1 <= thr[1][0]) { int p = atomicAdd(&s_cnt[s10], 1); if (p < MAXCAND) s_list[s10 * MAXCAND + p] = j1; }
                    if (dB2 <= thr[1][1]) { int p = atomicAdd(&s_cnt[s11], 1); if (p < MAXCAND) s_list[s11 * MAXCAND + p] = j0; }
                    if (dB3 <= thr[1][1]) { int p = atomicAdd(&s_cnt[s11], 1); if (p < MAXCAND) s_list[s11 * MAXCAND + p] = j1; }
                }
                if (pass == 0) {
                    m1[0][0] = fminf(m1[0][0], fminf(dA0, dA1));
                    m1[0][1] = fminf(m1[0][1], fminf(dA2, dA3));
                    m1[1][0] = fminf(m1[1][0], fminf(dB0, dB1));
                    m1[1][1] = fminf(m1[1][1], fminf(dB2, dB3));
                }
            }
            if (pass == 0) {
                // chunk-end quad-merge: row-global m1 -> tightened threshold
#pragma unroll
                for (int T = 0; T < 2; T++)
#pragma unroll
                    for (int r = 0; r < 2; r++) {
                        float v = m1[T][r];
                        v = fminf(v, __shfl_xor_sync(~0u, v, 1));
                        v = fminf(v, __shfl_xor_sync(~0u, v, 2));
                        m1[T][r] = v;
                        thr[T][r] = v + WIN;
                    }
            }
        }
    }
    __syncthreads();

    // ---- exact rescore + epilogue: thread tid owns block-token slot tid ----
    const int gid = blkTok + tid;
    float4 x4[16];
    const float4* xp = reinterpret_cast<const float4*>(inputs + (size_t)gid * D_EMB);
#pragma unroll
    for (int i = 0; i < 16; i++) x4[i] = xp[i];

    float best = 3.4028235e38f;
    int   bi = 0;
    const int cnt = s_cnt[tid];
    if (cnt <= MAXCAND) {
        for (int c = 0; c < cnt; c++) {
            int j = s_list[tid * MAXCAND + c];
            float d = exact_d(x4, codebook + (size_t)j * D_EMB, g_cnorm[j]);
            if (d < best || (d == best && j < bi)) { best = d; bi = j; }
        }
    } else {
        // overflow fallback: exact full scan, ascending j, strict <
        for (int j = 0; j < K_CB; j++) {
            float d = exact_d(x4, codebook + (size_t)j * D_EMB, g_cnorm[j]);
            if (d < best) { best = d; bi = j; }
        }
    }

    atomicAdd(&g_counts[bi], 1.0f);

    const float4* cch = reinterpret_cast<const float4*>(codebook + (size_t)bi * D_EMB);
    float4* qout = reinterpret_cast<float4*>(out + OFF_Q + (size_t)gid * D_EMB);
    float* dwrow = g_dw + (size_t)bi * D_EMB;
    float lsum = 0.0f;
#pragma unroll
    for (int i = 0; i < 16; i++) {
        float4 c4 = cch[i];
        qout[i] = c4;
        float dx = c4.x - x4[i].x, dy = c4.y - x4[i].y;
        float dz = c4.z - x4[i].z, dwv = c4.w - x4[i].w;
        lsum += dx * dx + dy * dy + dz * dz + dwv * dwv;
        atomicAdd(dwrow + 4 * i + 0, x4[i].x);
        atomicAdd(dwrow + 4 * i + 1, x4[i].y);
        atomicAdd(dwrow + 4 * i + 2, x4[i].z);
        atomicAdd(dwrow + 4 * i + 3, x4[i].w);
    }
    out[OFF_IDX + gid] = (float)bi;

    // block loss reduction
#pragma unroll
    for (int o = 16; o > 0; o >>= 1)
        lsum += __shfl_xor_sync(~0u, lsum, o);
    if (lane == 0) s_red[warp] = lsum;
    __syncthreads();
    if (tid == 0) {
        float t = 0.f;
#pragma unroll
        for (int w = 0; w < SC_TPB / 32; w++) t += s_red[w];
        atomicAdd(&g_loss, t);
    }
}

// ---------------------------------------------------------------------------
// Finalize stage 1: new_cluster_size, n-reduction, loss. One block.
// ---------------------------------------------------------------------------
__global__ void __launch_bounds__(K_CB)
vq_ncs_kernel(const float* __restrict__ ema_cs, float* __restrict__ out) {
    __shared__ float s_n[K_CB];
    const int k = threadIdx.x;

    float ncs = DECAY * ema_cs[k] + (1.0f - DECAY) * g_counts[k];
    out[OFF_CS + k] = ncs;

    s_n[k] = ncs;
    __syncthreads();
#pragma unroll
    for (int s = K_CB / 2; s > 0; s >>= 1) {
        if (k < s) s_n[k] += s_n[k + s];
        __syncthreads();
    }
    if (k == 0) {
        g_n = s_n[0];
        out[OFF_LOSS] = COMMIT * g_loss / (float)((size_t)N_TOK * D_EMB);
    }
}

// ---------------------------------------------------------------------------
// Finalize stage 2: element-parallel EMA weight + codebook update.
// ---------------------------------------------------------------------------
__global__ void __launch_bounds__(256)
vq_update_kernel(const float* __restrict__ ema_w, float* __restrict__ out) {
    const int idx = blockIdx.x * 256 + threadIdx.x;   // 0 .. K*D-1
    const int k = idx >> 6;

    float ncs = out[OFF_CS + k];
    float n = g_n;
    float smoothed = (ncs + EPSV) / (n + (float)K_CB * EPSV) * n;

    float w = DECAY * ema_w[idx] + (1.0f - DECAY) * g_dw[idx];
    out[OFF_EW + idx] = w;
    out[OFF_CB + idx] = w / smoothed;
}

// ---------------------------------------------------------------------------
extern "C" void kernel_launch(void* const* d_in, const int* in_sizes, int n_in,
                              void* d_out, int out_size) {
    const float* inputs   = (const float*)d_in[0];
    const float* codebook = (const float*)d_in[1];
    const float* ema_cs   = (const float*)d_in[2];
    const float* ema_w    = (const float*)d_in[3];
    float* out = (float*)d_out;

    vq_zero_kernel<<<(K_CB * D_EMB + 255) / 256, 256>>>();
    vq_prep_cb_kernel<<<1, K_CB>>>(codebook);
    vq_prep_x_kernel<<<N_TOK / 256, 256>>>(inputs);
    vq_screen_kernel<<<N_TOK / SC_TOKS, SC_TPB>>>(inputs, codebook, out);
    vq_ncs_kernel<<<1, K_CB>>>(ema_cs, out);
    vq_update_kernel<<<(K_CB * D_EMB) / 256, 256>>>(ema_w, out);
}

// round 15
// speedup vs baseline: 2.1072x; 2.1072x over previous
#include <cuda_runtime.h>
#include <cstdint>

// Problem constants
#define N_TOK  262144
#define K_CB   1024
#define D_EMB  64
#define DECAY  0.99f
#define EPSV   1e-5f
#define COMMIT 0.25f

// Output layout (float32 blob, reference return order)
#define OFF_Q    0
#define OFF_LOSS 16777216
#define OFF_IDX  16777217
#define OFF_CB   17039361   // odd -> only 4-byte aligned
#define OFF_CS   17104897
#define OFF_EW   17105921   // odd -> only 4-byte aligned

#define SEGW 12   // bf16 fragment segment: 8 payload words + 4 pad = 48B stride

// Scratch (device globals; no allocations allowed)
__device__ float    g_dw[K_CB * D_EMB];
__device__ float    g_counts[K_CB];
__device__ float    g_loss;
__device__ float    g_cnorm[K_CB];
__device__ float    g_n;
// codebook bf16-pairs, PADDED fragment-major for m16n8k16:
// seg = (code>>3)*32 + (code&7)*4 + tq ; word w (0..7): q=w>>1, reg=w&1,
// packs bf16(cb[d0]),bf16(cb[d0+1]) with d0 = 16q + 2tq + 8reg.
__device__ __align__(16) unsigned g_cbtp[(K_CB / 8) * 32 * SEGW];
__device__ unsigned g_xmax2;               // max ||x||^2 (float bits)
__device__ unsigned g_cmax2;               // max ||c||^2 (float bits)

// ---------------------------------------------------------------------------
__device__ __forceinline__ unsigned pack_bf16(float lo, float hi) {
    unsigned r;
    asm("cvt.rn.bf16x2.f32 %0, %1, %2;" : "=r"(r) : "f"(hi), "f"(lo));
    return r;
}

__device__ __forceinline__ void mma_bf16(float c[4], const unsigned a[4],
                                         unsigned b0, unsigned b1) {
    asm volatile(
        "mma.sync.aligned.m16n8k16.row.col.f32.bf16.bf16.f32 "
        "{%0,%1,%2,%3}, {%4,%5,%6,%7}, {%8,%9}, {%0,%1,%2,%3};"
        : "+f"(c[0]), "+f"(c[1]), "+f"(c[2]), "+f"(c[3])
        : "r"(a[0]), "r"(a[1]), "r"(a[2]), "r"(a[3]), "r"(b0), "r"(b1));
}

// Exact distance, bit-identical to the validated R2 chain ordering.
__device__ __forceinline__ float exact_d(const float4* x4, const float* crow, float cn) {
    const float4* c4 = reinterpret_cast<const float4*>(crow);
    float s0 = 0.f, s1 = 0.f, s2 = 0.f, s3 = 0.f;
#pragma unroll
    for (int i = 0; i < 16; i++) {
        float4 c = c4[i];
        s0 = fmaf(x4[i].x, c.x, s0);
        s1 = fmaf(x4[i].y, c.y, s1);
        s2 = fmaf(x4[i].z, c.z, s2);
        s3 = fmaf(x4[i].w, c.w, s3);
    }
    return cn - 2.0f * ((s0 + s1) + (s2 + s3));
}

// ---------------------------------------------------------------------------
__global__ void vq_zero_kernel() {
    int i = blockIdx.x * blockDim.x + threadIdx.x;
    if (i < K_CB * D_EMB) g_dw[i] = 0.0f;
    if (i < K_CB)         g_counts[i] = 0.0f;
    if (i == 0) { g_loss = 0.0f; g_xmax2 = 0u; g_cmax2 = 0u; }
}

// ---------------------------------------------------------------------------
// Prep codebook: exact cnorm (R2 chain), bf16 fragment-major scatter, max cn.
// One block of 1024 threads (one code per thread).
// ---------------------------------------------------------------------------
__global__ void __launch_bounds__(K_CB)
vq_prep_cb_kernel(const float* __restrict__ codebook) {
    __shared__ float s_m[32];
    int k = threadIdx.x;
    const float* cb = codebook + (size_t)k * D_EMB;
    const float4* c = reinterpret_cast<const float4*>(cb);
    float s0 = 0.f, s1 = 0.f, s2 = 0.f, s3 = 0.f;
#pragma unroll
    for (int i = 0; i < 16; i++) {
        float4 v = c[i];
        s0 += v.x * v.x; s1 += v.y * v.y;
        s2 += v.z * v.z; s3 += v.w * v.w;
    }
    float cn = (s0 + s1) + (s2 + s3);
    g_cnorm[k] = cn;
    // bf16 fragment-major scatter
    const int segbase = ((k >> 3) << 5) + ((k & 7) << 2);
#pragma unroll
    for (int tq = 0; tq < 4; tq++) {
#pragma unroll
        for (int w = 0; w < 8; w++) {
            int q = w >> 1, reg = w & 1;
            int d0 = 16 * q + 2 * tq + 8 * reg;
            g_cbtp[(size_t)(segbase + tq) * SEGW + w] = pack_bf16(cb[d0], cb[d0 + 1]);
        }
    }
    float m = cn;
#pragma unroll
    for (int o = 16; o > 0; o >>= 1) m = fmaxf(m, __shfl_xor_sync(~0u, m, o));
    if ((k & 31) == 0) s_m[k >> 5] = m;
    __syncthreads();
    if (k == 0) {
        float t = s_m[0];
        for (int w = 1; w < 32; w++) t = fmaxf(t, s_m[w]);
        atomicMax(&g_cmax2, __float_as_uint(t));
    }
}

// ---------------------------------------------------------------------------
// Prep inputs: max ||x||^2 over all tokens.
// ---------------------------------------------------------------------------
__global__ void __launch_bounds__(256)
vq_prep_x_kernel(const float* __restrict__ inputs) {
    __shared__ float s_m[8];
    int t = blockIdx.x * 256 + threadIdx.x;
    const float4* x = reinterpret_cast<const float4*>(inputs + (size_t)t * D_EMB);
    float s = 0.f;
#pragma unroll
    for (int i = 0; i < 16; i++) {
        float4 v = x[i];
        s += v.x * v.x + v.y * v.y + v.z * v.z + v.w * v.w;
    }
#pragma unroll
    for (int o = 16; o > 0; o >>= 1) s = fmaxf(s, __shfl_xor_sync(~0u, s, o));
    if ((threadIdx.x & 31) == 0) s_m[threadIdx.x >> 5] = s;
    __syncthreads();
    if (threadIdx.x == 0) {
        float m = s_m[0];
        for (int w = 1; w < 8; w++) m = fmaxf(m, s_m[w]);
        atomicMax(&g_xmax2, __float_as_uint(m));
    }
}

// ---------------------------------------------------------------------------
// Screen kernel — R13 two-sweep structure, bf16 m16n8k16 screen GEMM:
//   sweep 0: per-token min of d~ (bf16 screen; |d~ - d_exact| <= W)
//   sweep 1: collect all j with d~ <= min + 2W into per-token lists
// W = 1.0e-2 * Xmax * Cmax + 1e-3  (bf16 rn-conversion bound ~2^-7 * ||x||||c||
// with ~28% margin). Exact rescore (validated R2 chain + first-min tie rule);
// overflow falls back to per-thread exact full scan. Fused epilogue.
// ---------------------------------------------------------------------------
#define SC_TPB   128
#define SC_TOKS  128
#define SC_CHUNK 128
#define MAXCAND  16
#define CHUNK_W  ((SC_CHUNK / 8) * 32 * SEGW)       // 6144 words per chunk
#define CHUNK_V  (CHUNK_W / 4)                       // 1536 uint4 per chunk

__global__ void __launch_bounds__(SC_TPB)
vq_screen_kernel(const float* __restrict__ inputs,
                 const float* __restrict__ codebook,
                 float* __restrict__ out) {
    __shared__ __align__(16) unsigned s_cb[CHUNK_W];  // 24KB staged chunk
    __shared__ float    s_cn[SC_CHUNK];
    __shared__ int      s_cnt[SC_TOKS];
    __shared__ int      s_list[SC_TOKS * MAXCAND];
    __shared__ float    s_red[SC_TPB / 32];

    const int tid  = threadIdx.x;
    const int warp = tid >> 5;
    const int lane = tid & 31;
    const int g    = lane >> 2;    // group id (row for A/C, code col for B)
    const int tq   = lane & 3;     // thread-in-group
    const int blkTok = blockIdx.x * SC_TOKS;
    const int tokBase = blkTok + warp * 32;

    if (tid < SC_TOKS) s_cnt[tid] = 0;

    // bf16 screen error bound
    const float W = 1.0e-2f * sqrtf(__uint_as_float(g_xmax2))
                            * sqrtf(__uint_as_float(g_cmax2)) + 1e-3f;
    const float WIN = 2.0f * W;

    // A fragments (bf16 pairs) for both token tiles, 4 k-steps
    unsigned afr[2][4][4];
#pragma unroll
    for (int T = 0; T < 2; T++) {
        const int r0 = tokBase + T * 16 + g;
        const int r1 = r0 + 8;
        const float* x0 = inputs + (size_t)r0 * D_EMB;
        const float* x1 = inputs + (size_t)r1 * D_EMB;
#pragma unroll
        for (int q = 0; q < 4; q++) {
            const int kb = 16 * q + 2 * tq;
            afr[T][q][0] = pack_bf16(x0[kb],     x0[kb + 1]);
            afr[T][q][1] = pack_bf16(x1[kb],     x1[kb + 1]);
            afr[T][q][2] = pack_bf16(x0[kb + 8], x0[kb + 9]);
            afr[T][q][3] = pack_bf16(x1[kb + 8], x1[kb + 9]);
        }
    }

    float rmin[2][2] = {{3.4e38f, 3.4e38f}, {3.4e38f, 3.4e38f}};
    float thr[2][2]  = {{0.f, 0.f}, {0.f, 0.f}};

    for (int sweep = 0; sweep < 2; sweep++) {
        for (int ch = 0; ch < K_CB / SC_CHUNK; ch++) {
            __syncthreads();
            // pure vectorized copy of the pre-scattered chunk
            {
                const uint4* src = reinterpret_cast<const uint4*>(g_cbtp + (size_t)ch * CHUNK_W);
                uint4* dst = reinterpret_cast<uint4*>(s_cb);
#pragma unroll
                for (int i = 0; i < CHUNK_V / SC_TPB; i++)
                    dst[tid + i * SC_TPB] = src[tid + i * SC_TPB];
            }
            if (tid < SC_CHUNK) s_cn[tid] = g_cnorm[ch * SC_CHUNK + tid];
            __syncthreads();

#pragma unroll 4
            for (int tile = 0; tile < SC_CHUNK / 8; tile++) {
                float c0[4] = {0.f, 0.f, 0.f, 0.f};
                float c1[4] = {0.f, 0.f, 0.f, 0.f};
                // per-lane B segment: seg index within chunk = tile*32 + lane
                const unsigned* seg = s_cb + (size_t)(tile * 32 + lane) * SEGW;
                uint4 w0 = *reinterpret_cast<const uint4*>(seg);
                uint4 w1 = *reinterpret_cast<const uint4*>(seg + 4);
                mma_bf16(c0, afr[0][0], w0.x, w0.y);  mma_bf16(c1, afr[1][0], w0.x, w0.y);
                mma_bf16(c0, afr[0][1], w0.z, w0.w);  mma_bf16(c1, afr[1][1], w0.z, w0.w);
                mma_bf16(c0, afr[0][2], w1.x, w1.y);  mma_bf16(c1, afr[1][2], w1.x, w1.y);
                mma_bf16(c0, afr[0][3], w1.z, w1.w);  mma_bf16(c1, afr[1][3], w1.z, w1.w);

                const int col0 = (tile << 3) + tq * 2;
                const int j0 = ch * SC_CHUNK + col0, j1 = j0 + 1;
                const float cn0 = s_cn[col0], cn1 = s_cn[col0 + 1];
                float dA0 = fmaf(-2.0f, c0[0], cn0), dA1 = fmaf(-2.0f, c0[1], cn1);
                float dA2 = fmaf(-2.0f, c0[2], cn0), dA3 = fmaf(-2.0f, c0[3], cn1);
                float dB0 = fmaf(-2.0f, c1[0], cn0), dB1 = fmaf(-2.0f, c1[1], cn1);
                float dB2 = fmaf(-2.0f, c1[2], cn0), dB3 = fmaf(-2.0f, c1[3], cn1);
                if (sweep == 0) {
                    rmin[0][0] = fminf(rmin[0][0], fminf(dA0, dA1));
                    rmin[0][1] = fminf(rmin[0][1], fminf(dA2, dA3));
                    rmin[1][0] = fminf(rmin[1][0], fminf(dB0, dB1));
                    rmin[1][1] = fminf(rmin[1][1], fminf(dB2, dB3));
                } else {
                    const int s00 = warp * 32 + g;         // tile0 row g
                    const int s01 = s00 + 8;               // tile0 row g+8
                    const int s10 = s00 + 16;              // tile1 row g
                    const int s11 = s00 + 24;              // tile1 row g+8
                    if (dA0 <= thr[0][0]) { int p = atomicAdd(&s_cnt[s00], 1); if (p < MAXCAND) s_list[s00 * MAXCAND + p] = j0; }
                    if (dA1 <= thr[0][0]) { int p = atomicAdd(&s_cnt[s00], 1); if (p < MAXCAND) s_list[s00 * MAXCAND + p] = j1; }
                    if (dA2 <= thr[0][1]) { int p = atomicAdd(&s_cnt[s01], 1); if (p < MAXCAND) s_list[s01 * MAXCAND + p] = j0; }
                    if (dA3 <= thr[0][1]) { int p = atomicAdd(&s_cnt[s01], 1); if (p < MAXCAND) s_list[s01 * MAXCAND + p] = j1; }
                    if (dB0 <= thr[1][0]) { int p = atomicAdd(&s_cnt[s10], 1); if (p < MAXCAND) s_list[s10 * MAXCAND + p] = j0; }
                    if (dB1 <= thr[1][0]) { int p = atomicAdd(&s_cnt[s10], 1); if (p < MAXCAND) s_list[s10 * MAXCAND + p] = j1; }
                    if (dB2 <= thr[1][1]) { int p = atomicAdd(&s_cnt[s11], 1); if (p < MAXCAND) s_list[s11 * MAXCAND + p] = j0; }
                    if (dB3 <= thr[1][1]) { int p = atomicAdd(&s_cnt[s11], 1); if (p < MAXCAND) s_list[s11 * MAXCAND + p] = j1; }
                }
            }
        }
        if (sweep == 0) {
            // quad-reduce lane mins (cols) -> per-row global min -> thresholds
#pragma unroll
            for (int T = 0; T < 2; T++)
#pragma unroll
                for (int r = 0; r < 2; r++) {
                    float v = rmin[T][r];
                    v = fminf(v, __shfl_xor_sync(~0u, v, 1));
                    v = fminf(v, __shfl_xor_sync(~0u, v, 2));
                    thr[T][r] = v + WIN;
                }
        }
    }
    __syncthreads();

    // ---- exact rescore + epilogue: thread tid owns block-token slot tid ----
    const int gid = blkTok + tid;
    float4 x4[16];
    const float4* xp = reinterpret_cast<const float4*>(inputs + (size_t)gid * D_EMB);
#pragma unroll
    for (int i = 0; i < 16; i++) x4[i] = xp[i];

    float best = 3.4028235e38f;
    int   bi = 0;
    const int cnt = s_cnt[tid];
    if (cnt <= MAXCAND) {
        for (int c = 0; c < cnt; c++) {
            int j = s_list[tid * MAXCAND + c];
            float d = exact_d(x4, codebook + (size_t)j * D_EMB, g_cnorm[j]);
            if (d < best || (d == best && j < bi)) { best = d; bi = j; }
        }
    } else {
        // overflow fallback: exact full scan, ascending j, strict <
        for (int j = 0; j < K_CB; j++) {
            float d = exact_d(x4, codebook + (size_t)j * D_EMB, g_cnorm[j]);
            if (d < best) { best = d; bi = j; }
        }
    }

    atomicAdd(&g_counts[bi], 1.0f);

    const float4* cch = reinterpret_cast<const float4*>(codebook + (size_t)bi * D_EMB);
    float4* qout = reinterpret_cast<float4*>(out + OFF_Q + (size_t)gid * D_EMB);
    float* dwrow = g_dw + (size_t)bi * D_EMB;
    float lsum = 0.0f;
#pragma unroll
    for (int i = 0; i < 16; i++) {
        float4 c4 = cch[i];
        qout[i] = c4;
        float dx = c4.x - x4[i].x, dy = c4.y - x4[i].y;
        float dz = c4.z - x4[i].z, dwv = c4.w - x4[i].w;
        lsum += dx * dx + dy * dy + dz * dz + dwv * dwv;
        atomicAdd(dwrow + 4 * i + 0, x4[i].x);
        atomicAdd(dwrow + 4 * i + 1, x4[i].y);
        atomicAdd(dwrow + 4 * i + 2, x4[i].z);
        atomicAdd(dwrow + 4 * i + 3, x4[i].w);
    }
    out[OFF_IDX + gid] = (float)bi;

    // block loss reduction
#pragma unroll
    for (int o = 16; o > 0; o >>= 1)
        lsum += __shfl_xor_sync(~0u, lsum, o);
    if (lane == 0) s_red[warp] = lsum;
    __syncthreads();
    if (tid == 0) {
        float t = 0.f;
#pragma unroll
        for (int w = 0; w < SC_TPB / 32; w++) t += s_red[w];
        atomicAdd(&g_loss, t);
    }
}

// ---------------------------------------------------------------------------
// Finalize stage 1: new_cluster_size, n-reduction, loss. One block.
// ---------------------------------------------------------------------------
__global__ void __launch_bounds__(K_CB)
vq_ncs_kernel(const float* __restrict__ ema_cs, float* __restrict__ out) {
    __shared__ float s_n[K_CB];
    const int k = threadIdx.x;

    float ncs = DECAY * ema_cs[k] + (1.0f - DECAY) * g_counts[k];
    out[OFF_CS + k] = ncs;

    s_n[k] = ncs;
    __syncthreads();
#pragma unroll
    for (int s = K_CB / 2; s > 0; s >>= 1) {
        if (k < s) s_n[k] += s_n[k + s];
        __syncthreads();
    }
    if (k == 0) {
        g_n = s_n[0];
        out[OFF_LOSS] = COMMIT * g_loss / (float)((size_t)N_TOK * D_EMB);
    }
}

// ---------------------------------------------------------------------------
// Finalize stage 2: element-parallel EMA weight + codebook update.
// ---------------------------------------------------------------------------
__global__ void __launch_bounds__(256)
vq_update_kernel(const float* __restrict__ ema_w, float* __restrict__ out) {
    const int idx = blockIdx.x * 256 + threadIdx.x;   // 0 .. K*D-1
    const int k = idx >> 6;

    float ncs = out[OFF_CS + k];
    float n = g_n;
    float smoothed = (ncs + EPSV) / (n + (float)K_CB * EPSV) * n;

    float w = DECAY * ema_w[idx] + (1.0f - DECAY) * g_dw[idx];
    out[OFF_EW + idx] = w;
    out[OFF_CB + idx] = w / smoothed;
}

// ---------------------------------------------------------------------------
extern "C" void kernel_launch(void* const* d_in, const int* in_sizes, int n_in,
                              void* d_out, int out_size) {
    const float* inputs   = (const float*)d_in[0];
    const float* codebook = (const float*)d_in[1];
    const float* ema_cs   = (const float*)d_in[2];
    const float* ema_w    = (const float*)d_in[3];
    float* out = (float*)d_out;

    vq_zero_kernel<<<(K_CB * D_EMB + 255) / 256, 256>>>();
    vq_prep_cb_kernel<<<1, K_CB>>>(codebook);
    vq_prep_x_kernel<<<N_TOK / 256, 256>>>(inputs);
    vq_screen_kernel<<<N_TOK / SC_TOKS, SC_TPB>>>(inputs, codebook, out);
    vq_ncs_kernel<<<1, K_CB>>>(ema_cs, out);
    vq_update_kernel<<<(K_CB * D_EMB) / 256, 256>>>(ema_w, out);
}